// round 14
// baseline (speedup 1.0000x reference)
#include <cuda_runtime.h>
#include <math.h>
#include <float.h>

#define B 32
#define Q 1000
#define G 64
#define HT 256
#define NW (HT / 32)
#define FR_CAP 256
#define FULLM 0xffffffffu
#define KMAX 0xFFFFFFFFFFFFFFFFull

// global scratch (no cudaMalloc allowed)
__device__ float  g_v[B][Q];
__device__ float  g_u[B][G];
__device__ short  g_r4c[B][Q];
__device__ short  g_c4r[B][G];
__device__ double g_part[B * 3];
__device__ int    g_done = 0;

// ---- orderable float encoding: unsigned compare == float compare ----
__device__ __forceinline__ unsigned fenc(float f) {
    unsigned u = __float_as_uint(f);
    return (u & 0x80000000u) ? ~u : (u | 0x80000000u);
}
__device__ __forceinline__ float fdec(unsigned u) {
    u = (u & 0x80000000u) ? (u & 0x7fffffffu) : ~u;
    return __uint_as_float(u);
}
__device__ __forceinline__ unsigned long long fkey(float f, int j) {
    return ((unsigned long long)fenc(f) << 32) | (unsigned)j;
}
__device__ __forceinline__ float kval(unsigned long long k) { return fdec((unsigned)(k >> 32)); }
__device__ __forceinline__ int kidx(unsigned long long k) { return (int)(k & 0xffffffffu); }
__device__ __forceinline__ unsigned long long umin64(unsigned long long a, unsigned long long b) { return a < b ? a : b; }
__device__ __forceinline__ unsigned long long umax64(unsigned long long a, unsigned long long b) { return a > b ? a : b; }

// precise giou for the loss (matches reference math)
__device__ __forceinline__ float giou_ok(float ax1, float ay1, float ax2, float ay2,
                                         float bx1, float by1, float bx2, float by2) {
    float ix1 = fmaxf(ax1, bx1), iy1 = fmaxf(ay1, by1);
    float ix2 = fminf(ax2, bx2), iy2 = fminf(ay2, by2);
    float inter  = fmaxf(ix2 - ix1, 0.f) * fmaxf(iy2 - iy1, 0.f);
    float area_a = fmaxf(ax2 - ax1, 0.f) * fmaxf(ay2 - ay1, 0.f);
    float area_b = fmaxf(bx2 - bx1, 0.f) * fmaxf(by2 - by1, 0.f);
    float uni = area_a + area_b - inter + 1e-6f;
    float iou = inter / uni;
    float ex1 = fminf(ax1, bx1), ey1 = fminf(ay1, by1);
    float ex2 = fmaxf(ax2, bx2), ey2 = fmaxf(ay2, by2);
    float enc = fmaxf(fmaxf(ex2 - ex1, 0.f) * fmaxf(ey2 - ey1, 0.f), 1e-6f);
    return iou - (enc - uni) / enc;
}

// matching cost, single-division form (identical floats to R13 — passed)
__device__ __forceinline__ float costf(float4 p, float base2, float ap,
                                       float4 g, float gae) {
    float dx = fminf(p.z, g.z) - fmaxf(p.x, g.x);
    float dy = fminf(p.w, g.w) - fmaxf(p.y, g.y);
    float inter = fmaxf(dx, 0.f) * fmaxf(dy, 0.f);
    float uni = (ap + gae) - inter;
    float ex = fmaxf(p.z, g.z) - fminf(p.x, g.x);
    float ey = fmaxf(p.w, g.w) - fminf(p.y, g.y);
    float enc = fmaxf(fmaxf(ex, 0.f) * fmaxf(ey, 0.f), 1e-6f);
    float ratio = __fdividef(fmaf(uni, uni, inter * enc), uni * enc);
    float l1c = fabsf(p.x - g.x) + fabsf(p.y - g.y) +
                fabsf(p.z - g.z) + fabsf(p.w - g.w);
    return fmaf(-2.f, ratio, fmaf(5.f, l1c, base2));
}

__device__ __forceinline__ float sig_base2(const float* pl, int b, int j) {
    float l0 = pl[((size_t)b * Q + j) * 2 + 0];
    float l1 = pl[((size_t)b * Q + j) * 2 + 1];
    return 2.0f - 1.0f / (1.0f + __expf(l1 - l0));
}

// ===========================================================================
// k1: load + P1 (row minima) + P2 (greedy) + P3 (aug row reduction) -> scratch
// ===========================================================================
__global__ void __launch_bounds__(HT, 1) k1_reduce(
        const float* __restrict__ pb, const float* __restrict__ pl,
        const float* __restrict__ gb) {
    const int b = blockIdx.x;
    const int tid = threadIdx.x;
    const int lane = tid & 31, wid = tid >> 5;
    const float FINF = FLT_MAX;

    __shared__ float4 pbox4[Q];
    __shared__ float2 baux[Q];          // (base2, area_p)
    __shared__ float4 gt4s[G];
    __shared__ float  gae_s[G];
    __shared__ float  u_sh[G];
    __shared__ short  row4col[Q];
    __shared__ short  col4row[G];
    __shared__ float  umin[G];
    __shared__ int    uarg[G];
    __shared__ short  freerows[FR_CAP];
    __shared__ unsigned long long sl1[2][NW], sl2[2][NW];
    __shared__ int    nfree_sh;

    for (int j = tid; j < Q; j += HT) {
        float4 p = *reinterpret_cast<const float4*>(pb + ((size_t)b * Q + j) * 4);
        pbox4[j] = p;
        float ap = fmaxf(p.z - p.x, 0.f) * fmaxf(p.w - p.y, 0.f);
        baux[j] = make_float2(sig_base2(pl, b, j), ap);
        row4col[j] = -1;
    }
    if (tid < G) {
        float4 g = *reinterpret_cast<const float4*>(gb + ((size_t)b * G + tid) * 4);
        gt4s[tid] = g;
        gae_s[tid] = fmaxf(g.z - g.x, 0.f) * fmaxf(g.w - g.y, 0.f) + 1e-6f;
    }
    __syncthreads();

    // register cache of owned columns
    const int nk = (tid < Q - 3 * HT) ? 4 : 3;
    float4 c_p[4]; float c_b[4], c_a[4], v_reg[4];
#pragma unroll
    for (int k = 0; k < 4; k++) {
        int j = tid + HT * k;
        if (j < Q) {
            c_p[k] = pbox4[j];
            float2 ba = baux[j];
            c_b[k] = ba.x; c_a[k] = ba.y;
        }
        v_reg[k] = 0.f;
    }

    // ---- P1: row minima, warp-per-row, REDUX reduce ----
    for (int r = wid; r < G; r += NW) {
        float4 g = gt4s[r]; float gae = gae_s[r];
        float best = FINF; int bj = Q;
        for (int j = lane; j < Q; j += 32) {
            float2 ba = baux[j];
            float c = costf(pbox4[j], ba.x, ba.y, g, gae);
            if (c < best) { best = c; bj = j; }
        }
        unsigned ev = fenc(best);
        unsigned vm = __reduce_min_sync(FULLM, ev);
        unsigned jl = (ev == vm) ? (unsigned)bj : 0x7fffffffu;
        unsigned jm = __reduce_min_sync(FULLM, jl);
        if (lane == 0) { umin[r] = fdec(vm); uarg[r] = (int)jm; }
    }
    __syncthreads();
    if (tid < G) u_sh[tid] = umin[tid];
    // ---- P2: greedy tight-edge assignment ----
    if (tid == 0) {
        int nf = 0;
        for (int r = 0; r < G; r++) {
            int j = uarg[r];
            if (row4col[j] < 0) { row4col[j] = (short)r; col4row[r] = (short)j; }
            else { col4row[r] = -1; freerows[nf++] = (short)r; }
        }
        nfree_sh = nf;
    }
    __syncthreads();

    // ---- P3: augmenting row reduction (u64 pair butterfly, reg v) ----
    {
        int idx = 0, cnt = nfree_sh, iters = 0, par = 0;
        while (idx < cnt && iters < 192) {
            iters++;
            int i = freerows[idx]; idx++;
            float4 g = gt4s[i]; float gae = gae_s[i];
            unsigned long long k1 = KMAX, k2 = KMAX;
#pragma unroll
            for (int k = 0; k < 4; k++) {
                if (k < nk) {
                    int j = tid + HT * k;
                    float red = costf(c_p[k], c_b[k], c_a[k], g, gae) - v_reg[k];
                    unsigned long long kk = fkey(red, j);
                    if (kk < k1) { k2 = k1; k1 = kk; }
                    else if (kk < k2) { k2 = kk; }
                }
            }
#pragma unroll
            for (int off = 16; off > 0; off >>= 1) {
                unsigned long long o1 = __shfl_xor_sync(FULLM, k1, off);
                unsigned long long o2 = __shfl_xor_sync(FULLM, k2, off);
                unsigned long long mx = umax64(k1, o1);
                k1 = umin64(k1, o1);
                k2 = umin64(mx, umin64(k2, o2));
            }
            if (lane == 0) { sl1[par][wid] = k1; sl2[par][wid] = k2; }
            __syncthreads();
            unsigned long long K1 = sl1[par][0], K2 = sl2[par][0];
#pragma unroll
            for (int k = 1; k < NW; k++) {
                unsigned long long o1 = sl1[par][k], o2 = sl2[par][k];
                unsigned long long mx = umax64(K1, o1);
                K1 = umin64(K1, o1);
                K2 = umin64(mx, umin64(K2, o2));
            }
            float m1 = kval(K1), m2 = kval(K2);
            int j1 = kidx(K1), j2 = kidx(K2);
            bool strict = (m1 < m2);
            int jt = j1;
            int i0 = row4col[jt];
            if (!strict && i0 >= 0 && j2 < Q) { jt = j2; i0 = row4col[jt]; }
            __syncthreads();   // order decision-reads before tid0's writes
            if (i0 >= 0) {
                if (strict) idx--;
                else if (cnt < FR_CAP) cnt++;
            }
            if (strict && ((jt & (HT - 1)) == tid)) v_reg[jt >> 8] -= (m2 - m1);
            if (tid == 0) {
                u_sh[i] = m2;
                row4col[jt] = (short)i; col4row[i] = (short)jt;
                if (i0 >= 0) {
                    col4row[i0] = -1;
                    if (strict) freerows[idx] = (short)i0;
                    else if (cnt - 1 < FR_CAP) freerows[cnt - 1] = (short)i0;
                }
            }
            par ^= 1;
            __syncthreads();
        }
    }

    // ---- writeback state ----
#pragma unroll
    for (int k = 0; k < 4; k++)
        if (k < nk) g_v[b][tid + HT * k] = v_reg[k];
    for (int j = tid; j < Q; j += HT) g_r4c[b][j] = row4col[j];
    if (tid < G) { g_u[b][tid] = u_sh[tid]; g_c4r[b][tid] = col4row[tid]; }
}

// ===========================================================================
// k2: P4 (shortest augmenting path for leftover rows)
// ===========================================================================
__global__ void __launch_bounds__(HT, 1) k2_sap(
        const float* __restrict__ pb, const float* __restrict__ pl,
        const float* __restrict__ gb) {
    const int b = blockIdx.x;
    const int tid = threadIdx.x;
    const int lane = tid & 31, wid = tid >> 5;
    const float FINF = FLT_MAX;

    __shared__ float4 gt4s[G];
    __shared__ float  gae_s[G];
    __shared__ float  u_sh[G];
    __shared__ short  path[Q];
    __shared__ short  row4col[Q];
    __shared__ short  col4row[G];
    __shared__ unsigned long long sl1[2][NW];

    for (int j = tid; j < Q; j += HT) row4col[j] = g_r4c[b][j];
    if (tid < G) {
        float4 g = *reinterpret_cast<const float4*>(gb + ((size_t)b * G + tid) * 4);
        gt4s[tid] = g;
        gae_s[tid] = fmaxf(g.z - g.x, 0.f) * fmaxf(g.w - g.y, 0.f) + 1e-6f;
        u_sh[tid] = g_u[b][tid];
        col4row[tid] = g_c4r[b][tid];
    }

    // register cache of owned columns (direct from global)
    const int nk = (tid < Q - 3 * HT) ? 4 : 3;
    float4 c_p[4]; float c_b[4], c_a[4], v_reg[4], spc_reg[4];
    int usedmask = 0;
#pragma unroll
    for (int k = 0; k < 4; k++) {
        int j = tid + HT * k;
        if (j < Q) {
            float4 p = *reinterpret_cast<const float4*>(pb + ((size_t)b * Q + j) * 4);
            c_p[k] = p;
            c_b[k] = sig_base2(pl, b, j);
            c_a[k] = fmaxf(p.z - p.x, 0.f) * fmaxf(p.w - p.y, 0.f);
            v_reg[k] = g_v[b][j];
        }
        spc_reg[k] = FINF;
    }
    __syncthreads();

    for (int cur = 0; cur < G; cur++) {
        if (col4row[cur] >= 0) continue;

        int i = cur, par = 0, sink = -1;
        float minVal = 0.f;

        while (true) {
            float muv = minVal - u_sh[i];
            float4 g = gt4s[i]; float gae = gae_s[i];
            float best = FINF; int bestj = 0x7FFFFFFF;
#pragma unroll
            for (int k = 0; k < 4; k++) {
                if (k < nk && !((usedmask >> k) & 1)) {
                    int j = tid + HT * k;
                    float r = muv + costf(c_p[k], c_b[k], c_a[k], g, gae) - v_reg[k];
                    float s = spc_reg[k];
                    if (r < s) { s = r; spc_reg[k] = r; path[j] = (short)i; }
                    if (s < best) { best = s; bestj = j; }
                }
            }
            // REDUX warp reduce: exact value + exact smallest-j tie-break
            unsigned ev = fenc(best);
            unsigned vm = __reduce_min_sync(FULLM, ev);
            unsigned jl = (ev == vm) ? (unsigned)bestj : 0x7fffffffu;
            unsigned jm = __reduce_min_sync(FULLM, jl);
            if (lane == 0) sl1[par][wid] = ((unsigned long long)vm << 32) | jm;
            __syncthreads();
            unsigned long long K = sl1[par][0];
#pragma unroll
            for (int k = 1; k < NW; k++) K = umin64(K, sl1[par][k]);
            minVal = kval(K);
            int j1 = kidx(K);
            if ((j1 & (HT - 1)) == tid) usedmask |= 1 << (j1 >> 8);
            par ^= 1;
            int nr = row4col[j1];
            if (nr < 0) { sink = j1; break; }
            i = nr;
        }
        __syncthreads();

        // dual updates + owner-private reset (reads row4col; before augment writes)
#pragma unroll
        for (int k = 0; k < 4; k++) {
            if (k < nk && ((usedmask >> k) & 1)) {
                int j = tid + HT * k;
                float d = minVal - spc_reg[k];
                int r = row4col[j];
                if (r >= 0) u_sh[r] += d;
                v_reg[k] -= d;
            }
            spc_reg[k] = FINF;
        }
        usedmask = 0;
        __syncthreads();
        if (tid == 0) {
            u_sh[cur] += minVal;
            int j = sink;
            while (true) {
                int i2 = path[j];
                row4col[j] = (short)i2;
                int tcol = col4row[i2];
                col4row[i2] = (short)j;
                j = tcol;
                if (i2 == cur) break;
            }
        }
        __syncthreads();
    }

    if (tid < G) g_c4r[b][tid] = col4row[tid];
}

// ===========================================================================
// k3: losses + finalize
// ===========================================================================
__global__ void __launch_bounds__(HT, 1) k3_losses(
        const float* __restrict__ pb, const float* __restrict__ pl,
        const float* __restrict__ gb, float* __restrict__ out) {
    const int b = blockIdx.x;
    const int tid = threadIdx.x;
    const int lane = tid & 31, wid = tid >> 5;
    __shared__ double wsum[NW][3];

    double cls = 0.0, bbox = 0.0, gio = 0.0;
    for (int q = tid; q < Q; q += HT) {
        float l0 = pl[((size_t)b * Q + q) * 2 + 0];
        float l1 = pl[((size_t)b * Q + q) * 2 + 1];
        float mx = fmaxf(l0, l1);
        float lse = mx + logf(expf(l0 - mx) + expf(l1 - mx));
        cls += 0.1 * (double)(lse - l1);
    }
    if (tid < G) {
        int g = tid;
        int q = g_c4r[b][g];
        float4 mg = *reinterpret_cast<const float4*>(gb + ((size_t)b * G + g) * 4);
        float4 mp = *reinterpret_cast<const float4*>(pb + ((size_t)b * Q + q) * 4);
        bbox = (double)(fabsf(mp.x - mg.x) + fabsf(mp.y - mg.y) +
                        fabsf(mp.z - mg.z) + fabsf(mp.w - mg.w));
        gio = 1.0 - (double)giou_ok(mp.x, mp.y, mp.z, mp.w, mg.x, mg.y, mg.z, mg.w);
        float l0 = pl[((size_t)b * Q + q) * 2 + 0];
        float l1 = pl[((size_t)b * Q + q) * 2 + 1];
        float mx = fmaxf(l0, l1);
        float lse = mx + logf(expf(l0 - mx) + expf(l1 - mx));
        cls += (double)(lse - l0) - 0.1 * (double)(lse - l1);
    }
#pragma unroll
    for (int off = 16; off > 0; off >>= 1) {
        cls  += __shfl_down_sync(FULLM, cls, off);
        bbox += __shfl_down_sync(FULLM, bbox, off);
        gio  += __shfl_down_sync(FULLM, gio, off);
    }
    if (lane == 0) { wsum[wid][0] = cls; wsum[wid][1] = bbox; wsum[wid][2] = gio; }
    __syncthreads();

    if (tid == 0) {
        double cls_t = 0.0, bbox_t = 0.0, gio_t = 0.0;
        for (int w = 0; w < NW; w++) {
            cls_t += wsum[w][0]; bbox_t += wsum[w][1]; gio_t += wsum[w][2];
        }
        g_part[b * 3 + 0] = cls_t;
        g_part[b * 3 + 1] = bbox_t;
        g_part[b * 3 + 2] = gio_t;
        __threadfence();
        int prev = atomicAdd(&g_done, 1);
        if (prev == B - 1) {
            g_done = 0;
            __threadfence();
            double csum = 0.0, bsum = 0.0, gsum = 0.0;
            for (int k = 0; k < B; k++) {
                csum += g_part[k * 3 + 0];
                bsum += g_part[k * 3 + 1];
                gsum += g_part[k * 3 + 2];
            }
            const double wt_sum = 64.0 + (double)(Q - G) * 0.1;  // 157.6
            double lc = (csum / wt_sum) / (double)B;
            double nb = (double)(B * G);
            double lb = bsum / nb;
            double lg = gsum / nb;
            out[0] = (float)(1.0 * lc + 5.0 * lb + 2.0 * lg);
            out[1] = (float)lc;
            out[2] = (float)lb;
            out[3] = (float)lg;
        }
    }
}

// ---------------------------------------------------------------------------
extern "C" void kernel_launch(void* const* d_in, const int* in_sizes, int n_in,
                              void* d_out, int out_size) {
    const float* pred_boxes  = (const float*)d_in[0];  // [32,1000,4]
    const float* pred_logits = (const float*)d_in[1];  // [32,1000,2]
    const float* gt_boxes    = (const float*)d_in[2];  // [32,64,4]
    float* out = (float*)d_out;

    k1_reduce<<<B, HT>>>(pred_boxes, pred_logits, gt_boxes);
    k2_sap<<<B, HT>>>(pred_boxes, pred_logits, gt_boxes);
    k3_losses<<<B, HT>>>(pred_boxes, pred_logits, gt_boxes, out);
}

// round 15
// speedup vs baseline: 1.0812x; 1.0812x over previous
#include <cuda_runtime.h>
#include <math.h>
#include <float.h>

#define B 32
#define Q 1000
#define G 64
#define HT 256
#define NW (HT / 32)
#define FR_CAP 256
#define P3_CAP 48
#define FULLM 0xffffffffu
#define KMAX 0xFFFFFFFFFFFFFFFFull

__device__ double g_part[B * 3];
__device__ int    g_done = 0;

// ---- orderable float encoding: unsigned compare == float compare ----
__device__ __forceinline__ unsigned fenc(float f) {
    unsigned u = __float_as_uint(f);
    return (u & 0x80000000u) ? ~u : (u | 0x80000000u);
}
__device__ __forceinline__ float fdec(unsigned u) {
    u = (u & 0x80000000u) ? (u & 0x7fffffffu) : ~u;
    return __uint_as_float(u);
}
__device__ __forceinline__ unsigned long long fkey(float f, int j) {
    return ((unsigned long long)fenc(f) << 32) | (unsigned)j;
}
__device__ __forceinline__ float kval(unsigned long long k) { return fdec((unsigned)(k >> 32)); }
__device__ __forceinline__ int kidx(unsigned long long k) { return (int)(k & 0xffffffffu); }
__device__ __forceinline__ unsigned long long umin64(unsigned long long a, unsigned long long b) { return a < b ? a : b; }
__device__ __forceinline__ unsigned long long umax64(unsigned long long a, unsigned long long b) { return a > b ? a : b; }

// precise giou for the loss (matches reference math)
__device__ __forceinline__ float giou_ok(float ax1, float ay1, float ax2, float ay2,
                                         float bx1, float by1, float bx2, float by2) {
    float ix1 = fmaxf(ax1, bx1), iy1 = fmaxf(ay1, by1);
    float ix2 = fminf(ax2, bx2), iy2 = fminf(ay2, by2);
    float inter  = fmaxf(ix2 - ix1, 0.f) * fmaxf(iy2 - iy1, 0.f);
    float area_a = fmaxf(ax2 - ax1, 0.f) * fmaxf(ay2 - ay1, 0.f);
    float area_b = fmaxf(bx2 - bx1, 0.f) * fmaxf(by2 - by1, 0.f);
    float uni = area_a + area_b - inter + 1e-6f;
    float iou = inter / uni;
    float ex1 = fminf(ax1, bx1), ey1 = fminf(ay1, by1);
    float ex2 = fmaxf(ax2, bx2), ey2 = fmaxf(ay2, by2);
    float enc = fmaxf(fmaxf(ex2 - ex1, 0.f) * fmaxf(ey2 - ey1, 0.f), 1e-6f);
    return iou - (enc - uni) / enc;
}

// matching cost, single-division form (identical floats to R13 — passed)
__device__ __forceinline__ float costf(float4 p, float base2, float ap,
                                       float4 g, float gae) {
    float dx = fminf(p.z, g.z) - fmaxf(p.x, g.x);
    float dy = fminf(p.w, g.w) - fmaxf(p.y, g.y);
    float inter = fmaxf(dx, 0.f) * fmaxf(dy, 0.f);
    float uni = (ap + gae) - inter;
    float ex = fmaxf(p.z, g.z) - fminf(p.x, g.x);
    float ey = fmaxf(p.w, g.w) - fminf(p.y, g.y);
    float enc = fmaxf(fmaxf(ex, 0.f) * fmaxf(ey, 0.f), 1e-6f);
    float ratio = __fdividef(fmaf(uni, uni, inter * enc), uni * enc);
    float l1c = fabsf(p.x - g.x) + fabsf(p.y - g.y) +
                fabsf(p.z - g.z) + fabsf(p.w - g.w);
    return fmaf(-2.f, ratio, fmaf(5.f, l1c, base2));
}

// ---------------------------------------------------------------------------
__global__ void __launch_bounds__(HT, 1) match_kernel(
        const float* __restrict__ pb, const float* __restrict__ pl,
        const float* __restrict__ gb, float* __restrict__ out) {
    const int b = blockIdx.x;
    const int tid = threadIdx.x;
    const int lane = tid & 31, wid = tid >> 5;
    const float FINF = FLT_MAX;

    __shared__ float4 pbox4[Q];
    __shared__ float2 baux[Q];          // (base2 = 2-prob0, area_p)
    __shared__ float4 gt4s[G];
    __shared__ float  gae_s[G];         // garea + 1e-6
    __shared__ float  u_sh[G];
    __shared__ short  path[Q];
    __shared__ short  row4col[Q];
    __shared__ short  col4row[G];
    __shared__ float  umin[G];
    __shared__ int    uarg[G];
    __shared__ short  freerows[FR_CAP];
    __shared__ unsigned long long sl1[2][NW], sl2[2][NW];
    __shared__ double wsum[NW][3];
    __shared__ int    nfree_sh;

    // ---- load inputs ----
    for (int j = tid; j < Q; j += HT) {
        float4 p = *reinterpret_cast<const float4*>(pb + ((size_t)b * Q + j) * 4);
        pbox4[j] = p;
        float l0 = pl[((size_t)b * Q + j) * 2 + 0];
        float l1 = pl[((size_t)b * Q + j) * 2 + 1];
        float base = -1.0f / (1.0f + __expf(l1 - l0));
        float ap = fmaxf(p.z - p.x, 0.f) * fmaxf(p.w - p.y, 0.f);
        baux[j] = make_float2(base + 2.0f, ap);
        row4col[j] = -1;
    }
    if (tid < G) {
        float4 g = *reinterpret_cast<const float4*>(gb + ((size_t)b * G + tid) * 4);
        gt4s[tid] = g;
        gae_s[tid] = fmaxf(g.z - g.x, 0.f) * fmaxf(g.w - g.y, 0.f) + 1e-6f;
    }
    __syncthreads();

    // ---- register-cache this thread's 4 owned columns (j = tid + 256k) ----
    const int nk = (tid < Q - 3 * HT) ? 4 : 3;     // k=3 valid iff tid < 232
    float4 c_p[4]; float c_b[4], c_a[4], v_reg[4], spc_reg[4];
    int usedmask = 0;
#pragma unroll
    for (int k = 0; k < 4; k++) {
        int j = tid + HT * k;
        if (j < Q) {
            c_p[k] = pbox4[j];
            float2 ba = baux[j];
            c_b[k] = ba.x; c_a[k] = ba.y;
        }
        v_reg[k] = 0.f; spc_reg[k] = FINF;
    }

    // ---- P1: row minima, warp-per-row, REDUX reduce ----
    for (int r = wid; r < G; r += NW) {
        float4 g = gt4s[r]; float gae = gae_s[r];
        float best = FINF; int bj = Q;
        for (int j = lane; j < Q; j += 32) {
            float2 ba = baux[j];
            float c = costf(pbox4[j], ba.x, ba.y, g, gae);
            if (c < best) { best = c; bj = j; }
        }
        unsigned ev = fenc(best);
        unsigned vm = __reduce_min_sync(FULLM, ev);
        unsigned jl = (ev == vm) ? (unsigned)bj : 0x7fffffffu;
        unsigned jm = __reduce_min_sync(FULLM, jl);
        if (lane == 0) { umin[r] = fdec(vm); uarg[r] = (int)jm; }
    }
    __syncthreads();
    if (tid < G) u_sh[tid] = umin[tid];
    // ---- P2: greedy tight-edge assignment ----
    if (tid == 0) {
        int nf = 0;
        for (int r = 0; r < G; r++) {
            int j = uarg[r];
            if (row4col[j] < 0) { row4col[j] = (short)r; col4row[r] = (short)j; }
            else { col4row[r] = -1; freerows[nf++] = (short)r; }
        }
        nfree_sh = nf;
    }
    __syncthreads();

    // ---- P3: augmenting row reduction, CAPPED at ~2 passes (exactness-neutral) ----
    {
        int idx = 0, cnt = nfree_sh, iters = 0, par = 0;
        while (idx < cnt && iters < P3_CAP) {
            iters++;
            int i = freerows[idx]; idx++;
            float4 g = gt4s[i]; float gae = gae_s[i];
            unsigned long long k1 = KMAX, k2 = KMAX;
#pragma unroll
            for (int k = 0; k < 4; k++) {
                if (k < nk) {
                    int j = tid + HT * k;
                    float red = costf(c_p[k], c_b[k], c_a[k], g, gae) - v_reg[k];
                    unsigned long long kk = fkey(red, j);
                    if (kk < k1) { k2 = k1; k1 = kk; }
                    else if (kk < k2) { k2 = kk; }
                }
            }
#pragma unroll
            for (int off = 16; off > 0; off >>= 1) {
                unsigned long long o1 = __shfl_xor_sync(FULLM, k1, off);
                unsigned long long o2 = __shfl_xor_sync(FULLM, k2, off);
                unsigned long long mx = umax64(k1, o1);
                k1 = umin64(k1, o1);
                k2 = umin64(mx, umin64(k2, o2));
            }
            if (lane == 0) { sl1[par][wid] = k1; sl2[par][wid] = k2; }
            __syncthreads();
            unsigned long long K1 = sl1[par][0], K2 = sl2[par][0];
#pragma unroll
            for (int k = 1; k < NW; k++) {
                unsigned long long o1 = sl1[par][k], o2 = sl2[par][k];
                unsigned long long mx = umax64(K1, o1);
                K1 = umin64(K1, o1);
                K2 = umin64(mx, umin64(K2, o2));
            }
            float m1 = kval(K1), m2 = kval(K2);
            int j1 = kidx(K1), j2 = kidx(K2);
            bool strict = (m1 < m2);
            int jt = j1;
            int i0 = row4col[jt];
            if (!strict && i0 >= 0 && j2 < Q) { jt = j2; i0 = row4col[jt]; }
            __syncthreads();   // order decision-reads before tid0's writes
            if (i0 >= 0) {
                if (strict) idx--;
                else if (cnt < FR_CAP) cnt++;
            }
            if (strict && ((jt & (HT - 1)) == tid)) v_reg[jt >> 8] -= (m2 - m1);
            if (tid == 0) {
                u_sh[i] = m2;
                row4col[jt] = (short)i; col4row[i] = (short)jt;
                if (i0 >= 0) {
                    col4row[i0] = -1;
                    if (strict) freerows[idx] = (short)i0;
                    else if (cnt - 1 < FR_CAP) freerows[cnt - 1] = (short)i0;
                }
            }
            par ^= 1;
            __syncthreads();
        }
    }

    // ---- P4: SAP (reg spc/used/v; REDUX reduce; one barrier per pop) ----
    for (int cur = 0; cur < G; cur++) {
        if (col4row[cur] >= 0) continue;

        int i = cur, par = 0, sink = -1;
        float minVal = 0.f;

        while (true) {
            float muv = minVal - u_sh[i];
            float4 g = gt4s[i]; float gae = gae_s[i];
            float best = FINF; int bestj = 0x7FFFFFFF;
#pragma unroll
            for (int k = 0; k < 4; k++) {
                if (k < nk && !((usedmask >> k) & 1)) {
                    int j = tid + HT * k;
                    float r = muv + costf(c_p[k], c_b[k], c_a[k], g, gae) - v_reg[k];
                    float s = spc_reg[k];
                    if (r < s) { s = r; spc_reg[k] = r; path[j] = (short)i; }
                    if (s < best) { best = s; bestj = j; }
                }
            }
            unsigned ev = fenc(best);
            unsigned vm = __reduce_min_sync(FULLM, ev);
            unsigned jl = (ev == vm) ? (unsigned)bestj : 0x7fffffffu;
            unsigned jm = __reduce_min_sync(FULLM, jl);
            if (lane == 0) sl1[par][wid] = ((unsigned long long)vm << 32) | jm;
            __syncthreads();
            unsigned long long K = sl1[par][0];
#pragma unroll
            for (int k = 1; k < NW; k++) K = umin64(K, sl1[par][k]);
            minVal = kval(K);
            int j1 = kidx(K);
            if ((j1 & (HT - 1)) == tid) usedmask |= 1 << (j1 >> 8);
            par ^= 1;
            int nr = row4col[j1];     // row4col constant during pop loop
            if (nr < 0) { sink = j1; break; }
            i = nr;
        }
        __syncthreads();

        // dual updates + owner-private reset (reads row4col before augment writes)
#pragma unroll
        for (int k = 0; k < 4; k++) {
            if (k < nk && ((usedmask >> k) & 1)) {
                int j = tid + HT * k;
                float d = minVal - spc_reg[k];
                int r = row4col[j];
                if (r >= 0) u_sh[r] += d;
                v_reg[k] -= d;
            }
            spc_reg[k] = FINF;
        }
        usedmask = 0;
        __syncthreads();
        if (tid == 0) {
            u_sh[cur] += minVal;
            int j = sink;
            while (true) {
                int i2 = path[j];
                row4col[j] = (short)i2;
                int tcol = col4row[i2];
                col4row[i2] = (short)j;
                j = tcol;
                if (i2 == cur) break;
            }
        }
        __syncthreads();
    }

    // ---- fused per-batch losses (fp64) ----
    double cls = 0.0, bbox = 0.0, gio = 0.0;
    for (int q = tid; q < Q; q += HT) {
        float l0 = pl[((size_t)b * Q + q) * 2 + 0];
        float l1 = pl[((size_t)b * Q + q) * 2 + 1];
        float mx = fmaxf(l0, l1);
        float lse = mx + logf(expf(l0 - mx) + expf(l1 - mx));
        cls += 0.1 * (double)(lse - l1);
    }
    if (tid < G) {
        int g = tid;
        int q = col4row[g];
        float4 mg = gt4s[g];
        float4 mp = pbox4[q];
        bbox = (double)(fabsf(mp.x - mg.x) + fabsf(mp.y - mg.y) +
                        fabsf(mp.z - mg.z) + fabsf(mp.w - mg.w));
        gio = 1.0 - (double)giou_ok(mp.x, mp.y, mp.z, mp.w, mg.x, mg.y, mg.z, mg.w);
        float l0 = pl[((size_t)b * Q + q) * 2 + 0];
        float l1 = pl[((size_t)b * Q + q) * 2 + 1];
        float mx = fmaxf(l0, l1);
        float lse = mx + logf(expf(l0 - mx) + expf(l1 - mx));
        cls += (double)(lse - l0) - 0.1 * (double)(lse - l1);
    }
#pragma unroll
    for (int off = 16; off > 0; off >>= 1) {
        cls  += __shfl_down_sync(FULLM, cls, off);
        bbox += __shfl_down_sync(FULLM, bbox, off);
        gio  += __shfl_down_sync(FULLM, gio, off);
    }
    if (lane == 0) { wsum[wid][0] = cls; wsum[wid][1] = bbox; wsum[wid][2] = gio; }
    __syncthreads();

    if (tid == 0) {
        double cls_t = 0.0, bbox_t = 0.0, gio_t = 0.0;
        for (int w = 0; w < NW; w++) {
            cls_t += wsum[w][0]; bbox_t += wsum[w][1]; gio_t += wsum[w][2];
        }
        g_part[b * 3 + 0] = cls_t;
        g_part[b * 3 + 1] = bbox_t;
        g_part[b * 3 + 2] = gio_t;
        __threadfence();
        int prev = atomicAdd(&g_done, 1);
        if (prev == B - 1) {
            g_done = 0;
            __threadfence();
            double csum = 0.0, bsum = 0.0, gsum = 0.0;
            for (int k = 0; k < B; k++) {
                csum += g_part[k * 3 + 0];
                bsum += g_part[k * 3 + 1];
                gsum += g_part[k * 3 + 2];
            }
            const double wt_sum = 64.0 + (double)(Q - G) * 0.1;  // 157.6
            double lc = (csum / wt_sum) / (double)B;
            double nb = (double)(B * G);
            double lb = bsum / nb;
            double lg = gsum / nb;
            out[0] = (float)(1.0 * lc + 5.0 * lb + 2.0 * lg);
            out[1] = (float)lc;
            out[2] = (float)lb;
            out[3] = (float)lg;
        }
    }
}

// ---------------------------------------------------------------------------
extern "C" void kernel_launch(void* const* d_in, const int* in_sizes, int n_in,
                              void* d_out, int out_size) {
    const float* pred_boxes  = (const float*)d_in[0];  // [32,1000,4]
    const float* pred_logits = (const float*)d_in[1];  // [32,1000,2]
    const float* gt_boxes    = (const float*)d_in[2];  // [32,64,4]
    float* out = (float*)d_out;

    match_kernel<<<B, HT>>>(pred_boxes, pred_logits, gt_boxes, out);
}

// round 16
// speedup vs baseline: 1.3761x; 1.2727x over previous
#include <cuda_runtime.h>
#include <math.h>
#include <float.h>

#define B 32
#define Q 1000
#define G 64
#define HT 256
#define NW (HT / 32)
#define FR_CAP 256
#define P3_CAP 48
#define FULLM 0xffffffffu
#define KMAX 0xFFFFFFFFFFFFFFFFull

__device__ double g_part[B * 3];
__device__ int    g_done = 0;
__device__ float  g_umin[B][G];
__device__ int    g_uarg[B][G];

// ---- orderable float encoding: unsigned compare == float compare ----
__device__ __forceinline__ unsigned fenc(float f) {
    unsigned u = __float_as_uint(f);
    return (u & 0x80000000u) ? ~u : (u | 0x80000000u);
}
__device__ __forceinline__ float fdec(unsigned u) {
    u = (u & 0x80000000u) ? (u & 0x7fffffffu) : ~u;
    return __uint_as_float(u);
}
__device__ __forceinline__ unsigned long long fkey(float f, int j) {
    return ((unsigned long long)fenc(f) << 32) | (unsigned)j;
}
__device__ __forceinline__ float kval(unsigned long long k) { return fdec((unsigned)(k >> 32)); }
__device__ __forceinline__ int kidx(unsigned long long k) { return (int)(k & 0xffffffffu); }
__device__ __forceinline__ unsigned long long umin64(unsigned long long a, unsigned long long b) { return a < b ? a : b; }
__device__ __forceinline__ unsigned long long umax64(unsigned long long a, unsigned long long b) { return a > b ? a : b; }

// precise giou for the loss (matches reference math)
__device__ __forceinline__ float giou_ok(float ax1, float ay1, float ax2, float ay2,
                                         float bx1, float by1, float bx2, float by2) {
    float ix1 = fmaxf(ax1, bx1), iy1 = fmaxf(ay1, by1);
    float ix2 = fminf(ax2, bx2), iy2 = fminf(ay2, by2);
    float inter  = fmaxf(ix2 - ix1, 0.f) * fmaxf(iy2 - iy1, 0.f);
    float area_a = fmaxf(ax2 - ax1, 0.f) * fmaxf(ay2 - ay1, 0.f);
    float area_b = fmaxf(bx2 - bx1, 0.f) * fmaxf(by2 - by1, 0.f);
    float uni = area_a + area_b - inter + 1e-6f;
    float iou = inter / uni;
    float ex1 = fminf(ax1, bx1), ey1 = fminf(ay1, by1);
    float ex2 = fmaxf(ax2, bx2), ey2 = fmaxf(ay2, by2);
    float enc = fmaxf(fmaxf(ex2 - ex1, 0.f) * fmaxf(ey2 - ey1, 0.f), 1e-6f);
    return iou - (enc - uni) / enc;
}

// matching cost, single-division form (identical floats to R13/R15 — passed)
__device__ __forceinline__ float costf(float4 p, float base2, float ap,
                                       float4 g, float gae) {
    float dx = fminf(p.z, g.z) - fmaxf(p.x, g.x);
    float dy = fminf(p.w, g.w) - fmaxf(p.y, g.y);
    float inter = fmaxf(dx, 0.f) * fmaxf(dy, 0.f);
    float uni = (ap + gae) - inter;
    float ex = fmaxf(p.z, g.z) - fminf(p.x, g.x);
    float ey = fmaxf(p.w, g.w) - fminf(p.y, g.y);
    float enc = fmaxf(fmaxf(ex, 0.f) * fmaxf(ey, 0.f), 1e-6f);
    float ratio = __fdividef(fmaf(uni, uni, inter * enc), uni * enc);
    float l1c = fabsf(p.x - g.x) + fabsf(p.y - g.y) +
                fabsf(p.z - g.z) + fabsf(p.w - g.w);
    return fmaf(-2.f, ratio, fmaf(5.f, l1c, base2));
}

// ===========================================================================
// p1_kernel: row minima, massively parallel. grid (8, B), 256 thr.
// Warp w of block (rb, b) handles row r = rb*8 + w with the SAME lane mapping
// and REDUX reduction as the old in-monolith P1 -> bit-identical results.
// ===========================================================================
__global__ void __launch_bounds__(HT, 1) p1_kernel(
        const float* __restrict__ pb, const float* __restrict__ pl,
        const float* __restrict__ gb) {
    const int b = blockIdx.y;
    const int tid = threadIdx.x;
    const int lane = tid & 31, wid = tid >> 5;
    const float FINF = FLT_MAX;

    __shared__ float4 pbox4[Q];
    __shared__ float2 baux[Q];

    for (int j = tid; j < Q; j += HT) {
        float4 p = *reinterpret_cast<const float4*>(pb + ((size_t)b * Q + j) * 4);
        pbox4[j] = p;
        float l0 = pl[((size_t)b * Q + j) * 2 + 0];
        float l1 = pl[((size_t)b * Q + j) * 2 + 1];
        float base = -1.0f / (1.0f + __expf(l1 - l0));
        float ap = fmaxf(p.z - p.x, 0.f) * fmaxf(p.w - p.y, 0.f);
        baux[j] = make_float2(base + 2.0f, ap);
    }
    __syncthreads();

    const int r = blockIdx.x * NW + wid;
    float4 g = *reinterpret_cast<const float4*>(gb + ((size_t)b * G + r) * 4);
    float gae = fmaxf(g.z - g.x, 0.f) * fmaxf(g.w - g.y, 0.f) + 1e-6f;

    float best = FINF; int bj = Q;
#pragma unroll 4
    for (int j = lane; j < Q; j += 32) {
        float2 ba = baux[j];
        float c = costf(pbox4[j], ba.x, ba.y, g, gae);
        if (c < best) { best = c; bj = j; }
    }
    unsigned ev = fenc(best);
    unsigned vm = __reduce_min_sync(FULLM, ev);
    unsigned jl = (ev == vm) ? (unsigned)bj : 0x7fffffffu;
    unsigned jm = __reduce_min_sync(FULLM, jl);
    if (lane == 0) { g_umin[b][r] = fdec(vm); g_uarg[b][r] = (int)jm; }
}

// ===========================================================================
// match_kernel: P2 + P3 + P4 + losses (R15 matcher, P1 read from scratch)
// ===========================================================================
__global__ void __launch_bounds__(HT, 1) match_kernel(
        const float* __restrict__ pb, const float* __restrict__ pl,
        const float* __restrict__ gb, float* __restrict__ out) {
    const int b = blockIdx.x;
    const int tid = threadIdx.x;
    const int lane = tid & 31, wid = tid >> 5;
    const float FINF = FLT_MAX;

    __shared__ float4 pbox4[Q];
    __shared__ float2 baux[Q];
    __shared__ float4 gt4s[G];
    __shared__ float  gae_s[G];
    __shared__ float  u_sh[G];
    __shared__ short  path[Q];
    __shared__ short  row4col[Q];
    __shared__ short  col4row[G];
    __shared__ int    uarg[G];
    __shared__ short  freerows[FR_CAP];
    __shared__ unsigned long long sl1[2][NW], sl2[2][NW];
    __shared__ double wsum[NW][3];
    __shared__ int    nfree_sh;

    for (int j = tid; j < Q; j += HT) {
        float4 p = *reinterpret_cast<const float4*>(pb + ((size_t)b * Q + j) * 4);
        pbox4[j] = p;
        float l0 = pl[((size_t)b * Q + j) * 2 + 0];
        float l1 = pl[((size_t)b * Q + j) * 2 + 1];
        float base = -1.0f / (1.0f + __expf(l1 - l0));
        float ap = fmaxf(p.z - p.x, 0.f) * fmaxf(p.w - p.y, 0.f);
        baux[j] = make_float2(base + 2.0f, ap);
        row4col[j] = -1;
    }
    if (tid < G) {
        float4 g = *reinterpret_cast<const float4*>(gb + ((size_t)b * G + tid) * 4);
        gt4s[tid] = g;
        gae_s[tid] = fmaxf(g.z - g.x, 0.f) * fmaxf(g.w - g.y, 0.f) + 1e-6f;
        u_sh[tid] = g_umin[b][tid];
        uarg[tid] = g_uarg[b][tid];
    }
    __syncthreads();

    // register-cache this thread's 4 owned columns (j = tid + 256k)
    const int nk = (tid < Q - 3 * HT) ? 4 : 3;
    float4 c_p[4]; float c_b[4], c_a[4], v_reg[4], spc_reg[4];
    int usedmask = 0;
#pragma unroll
    for (int k = 0; k < 4; k++) {
        int j = tid + HT * k;
        if (j < Q) {
            c_p[k] = pbox4[j];
            float2 ba = baux[j];
            c_b[k] = ba.x; c_a[k] = ba.y;
        }
        v_reg[k] = 0.f; spc_reg[k] = FINF;
    }

    // ---- P2: greedy tight-edge assignment ----
    if (tid == 0) {
        int nf = 0;
        for (int r = 0; r < G; r++) {
            int j = uarg[r];
            if (row4col[j] < 0) { row4col[j] = (short)r; col4row[r] = (short)j; }
            else { col4row[r] = -1; freerows[nf++] = (short)r; }
        }
        nfree_sh = nf;
    }
    __syncthreads();

    // ---- P3: augmenting row reduction (capped; exactness-neutral) ----
    {
        int idx = 0, cnt = nfree_sh, iters = 0, par = 0;
        while (idx < cnt && iters < P3_CAP) {
            iters++;
            int i = freerows[idx]; idx++;
            float4 g = gt4s[i]; float gae = gae_s[i];
            unsigned long long k1 = KMAX, k2 = KMAX;
#pragma unroll
            for (int k = 0; k < 4; k++) {
                if (k < nk) {
                    int j = tid + HT * k;
                    float red = costf(c_p[k], c_b[k], c_a[k], g, gae) - v_reg[k];
                    unsigned long long kk = fkey(red, j);
                    if (kk < k1) { k2 = k1; k1 = kk; }
                    else if (kk < k2) { k2 = kk; }
                }
            }
#pragma unroll
            for (int off = 16; off > 0; off >>= 1) {
                unsigned long long o1 = __shfl_xor_sync(FULLM, k1, off);
                unsigned long long o2 = __shfl_xor_sync(FULLM, k2, off);
                unsigned long long mx = umax64(k1, o1);
                k1 = umin64(k1, o1);
                k2 = umin64(mx, umin64(k2, o2));
            }
            if (lane == 0) { sl1[par][wid] = k1; sl2[par][wid] = k2; }
            __syncthreads();
            unsigned long long K1 = sl1[par][0], K2 = sl2[par][0];
#pragma unroll
            for (int k = 1; k < NW; k++) {
                unsigned long long o1 = sl1[par][k], o2 = sl2[par][k];
                unsigned long long mx = umax64(K1, o1);
                K1 = umin64(K1, o1);
                K2 = umin64(mx, umin64(K2, o2));
            }
            float m1 = kval(K1), m2 = kval(K2);
            int j1 = kidx(K1), j2 = kidx(K2);
            bool strict = (m1 < m2);
            int jt = j1;
            int i0 = row4col[jt];
            if (!strict && i0 >= 0 && j2 < Q) { jt = j2; i0 = row4col[jt]; }
            __syncthreads();   // order decision-reads before tid0's writes
            if (i0 >= 0) {
                if (strict) idx--;
                else if (cnt < FR_CAP) cnt++;
            }
            if (strict && ((jt & (HT - 1)) == tid)) v_reg[jt >> 8] -= (m2 - m1);
            if (tid == 0) {
                u_sh[i] = m2;
                row4col[jt] = (short)i; col4row[i] = (short)jt;
                if (i0 >= 0) {
                    col4row[i0] = -1;
                    if (strict) freerows[idx] = (short)i0;
                    else if (cnt - 1 < FR_CAP) freerows[cnt - 1] = (short)i0;
                }
            }
            par ^= 1;
            __syncthreads();
        }
    }

    // ---- P4: SAP (reg spc/used/v; REDUX reduce; one barrier per pop) ----
    for (int cur = 0; cur < G; cur++) {
        if (col4row[cur] >= 0) continue;

        int i = cur, par = 0, sink = -1;
        float minVal = 0.f;

        while (true) {
            float muv = minVal - u_sh[i];
            float4 g = gt4s[i]; float gae = gae_s[i];
            float best = FINF; int bestj = 0x7FFFFFFF;
#pragma unroll
            for (int k = 0; k < 4; k++) {
                if (k < nk && !((usedmask >> k) & 1)) {
                    int j = tid + HT * k;
                    float r = muv + costf(c_p[k], c_b[k], c_a[k], g, gae) - v_reg[k];
                    float s = spc_reg[k];
                    if (r < s) { s = r; spc_reg[k] = r; path[j] = (short)i; }
                    if (s < best) { best = s; bestj = j; }
                }
            }
            unsigned ev = fenc(best);
            unsigned vm = __reduce_min_sync(FULLM, ev);
            unsigned jl = (ev == vm) ? (unsigned)bestj : 0x7fffffffu;
            unsigned jm = __reduce_min_sync(FULLM, jl);
            if (lane == 0) sl1[par][wid] = ((unsigned long long)vm << 32) | jm;
            __syncthreads();
            unsigned long long K = sl1[par][0];
#pragma unroll
            for (int k = 1; k < NW; k++) K = umin64(K, sl1[par][k]);
            minVal = kval(K);
            int j1 = kidx(K);
            if ((j1 & (HT - 1)) == tid) usedmask |= 1 << (j1 >> 8);
            par ^= 1;
            int nr = row4col[j1];
            if (nr < 0) { sink = j1; break; }
            i = nr;
        }
        __syncthreads();

        // dual updates + owner-private reset
#pragma unroll
        for (int k = 0; k < 4; k++) {
            if (k < nk && ((usedmask >> k) & 1)) {
                int j = tid + HT * k;
                float d = minVal - spc_reg[k];
                int r = row4col[j];
                if (r >= 0) u_sh[r] += d;
                v_reg[k] -= d;
            }
            spc_reg[k] = FINF;
        }
        usedmask = 0;
        __syncthreads();
        if (tid == 0) {
            u_sh[cur] += minVal;
            int j = sink;
            while (true) {
                int i2 = path[j];
                row4col[j] = (short)i2;
                int tcol = col4row[i2];
                col4row[i2] = (short)j;
                j = tcol;
                if (i2 == cur) break;
            }
        }
        __syncthreads();
    }

    // ---- fused per-batch losses (fp64) ----
    double cls = 0.0, bbox = 0.0, gio = 0.0;
    for (int q = tid; q < Q; q += HT) {
        float l0 = pl[((size_t)b * Q + q) * 2 + 0];
        float l1 = pl[((size_t)b * Q + q) * 2 + 1];
        float mx = fmaxf(l0, l1);
        float lse = mx + logf(expf(l0 - mx) + expf(l1 - mx));
        cls += 0.1 * (double)(lse - l1);
    }
    if (tid < G) {
        int g = tid;
        int q = col4row[g];
        float4 mg = gt4s[g];
        float4 mp = pbox4[q];
        bbox = (double)(fabsf(mp.x - mg.x) + fabsf(mp.y - mg.y) +
                        fabsf(mp.z - mg.z) + fabsf(mp.w - mg.w));
        gio = 1.0 - (double)giou_ok(mp.x, mp.y, mp.z, mp.w, mg.x, mg.y, mg.z, mg.w);
        float l0 = pl[((size_t)b * Q + q) * 2 + 0];
        float l1 = pl[((size_t)b * Q + q) * 2 + 1];
        float mx = fmaxf(l0, l1);
        float lse = mx + logf(expf(l0 - mx) + expf(l1 - mx));
        cls += (double)(lse - l0) - 0.1 * (double)(lse - l1);
    }
#pragma unroll
    for (int off = 16; off > 0; off >>= 1) {
        cls  += __shfl_down_sync(FULLM, cls, off);
        bbox += __shfl_down_sync(FULLM, bbox, off);
        gio  += __shfl_down_sync(FULLM, gio, off);
    }
    if (lane == 0) { wsum[wid][0] = cls; wsum[wid][1] = bbox; wsum[wid][2] = gio; }
    __syncthreads();

    if (tid == 0) {
        double cls_t = 0.0, bbox_t = 0.0, gio_t = 0.0;
        for (int w = 0; w < NW; w++) {
            cls_t += wsum[w][0]; bbox_t += wsum[w][1]; gio_t += wsum[w][2];
        }
        g_part[b * 3 + 0] = cls_t;
        g_part[b * 3 + 1] = bbox_t;
        g_part[b * 3 + 2] = gio_t;
        __threadfence();
        int prev = atomicAdd(&g_done, 1);
        if (prev == B - 1) {
            g_done = 0;
            __threadfence();
            double csum = 0.0, bsum = 0.0, gsum = 0.0;
            for (int k = 0; k < B; k++) {
                csum += g_part[k * 3 + 0];
                bsum += g_part[k * 3 + 1];
                gsum += g_part[k * 3 + 2];
            }
            const double wt_sum = 64.0 + (double)(Q - G) * 0.1;  // 157.6
            double lc = (csum / wt_sum) / (double)B;
            double nb = (double)(B * G);
            double lb = bsum / nb;
            double lg = gsum / nb;
            out[0] = (float)(1.0 * lc + 5.0 * lb + 2.0 * lg);
            out[1] = (float)lc;
            out[2] = (float)lb;
            out[3] = (float)lg;
        }
    }
}

// ---------------------------------------------------------------------------
extern "C" void kernel_launch(void* const* d_in, const int* in_sizes, int n_in,
                              void* d_out, int out_size) {
    const float* pred_boxes  = (const float*)d_in[0];  // [32,1000,4]
    const float* pred_logits = (const float*)d_in[1];  // [32,1000,2]
    const float* gt_boxes    = (const float*)d_in[2];  // [32,64,4]
    float* out = (float*)d_out;

    dim3 pgrid(G / NW, B);   // (8, 32) = 256 blocks
    p1_kernel<<<pgrid, HT>>>(pred_boxes, pred_logits, gt_boxes);
    match_kernel<<<B, HT>>>(pred_boxes, pred_logits, gt_boxes, out);
}

// round 17
// speedup vs baseline: 1.5385x; 1.1180x over previous
#include <cuda_runtime.h>
#include <math.h>
#include <float.h>

#define B 32
#define Q 1000
#define G 64
#define HT 256
#define NW (HT / 32)
#define FR_CAP 256
#define P3_CAP 48
#define FULLM 0xffffffffu
#define KMAX 0xFFFFFFFFFFFFFFFFull

__device__ double g_part[B * 3];
__device__ int    g_done = 0;
__device__ float  g_umin[B][G];
__device__ int    g_uarg[B][G];
__device__ float  g_cost[B][G][Q];    // row-major cost, written by p1_kernel

// ---- orderable float encoding ----
__device__ __forceinline__ unsigned fenc(float f) {
    unsigned u = __float_as_uint(f);
    return (u & 0x80000000u) ? ~u : (u | 0x80000000u);
}
__device__ __forceinline__ float fdec(unsigned u) {
    u = (u & 0x80000000u) ? (u & 0x7fffffffu) : ~u;
    return __uint_as_float(u);
}
__device__ __forceinline__ unsigned long long fkey(float f, int j) {
    return ((unsigned long long)fenc(f) << 32) | (unsigned)j;
}
__device__ __forceinline__ float kval(unsigned long long k) { return fdec((unsigned)(k >> 32)); }
__device__ __forceinline__ int kidx(unsigned long long k) { return (int)(k & 0xffffffffu); }
__device__ __forceinline__ unsigned long long umin64(unsigned long long a, unsigned long long b) { return a < b ? a : b; }
__device__ __forceinline__ unsigned long long umax64(unsigned long long a, unsigned long long b) { return a > b ? a : b; }

// warp min of 64-bit keys via 2x REDUX (value, then smallest index among ties)
__device__ __forceinline__ unsigned long long warp_kmin(unsigned long long k) {
    unsigned ev = (unsigned)(k >> 32);
    unsigned vm = __reduce_min_sync(FULLM, ev);
    unsigned jl = (ev == vm) ? (unsigned)(k & 0xffffffffu) : 0x7fffffffu;
    unsigned jm = __reduce_min_sync(FULLM, jl);
    return ((unsigned long long)vm << 32) | jm;
}

// precise giou for the loss (matches reference math)
__device__ __forceinline__ float giou_ok(float ax1, float ay1, float ax2, float ay2,
                                         float bx1, float by1, float bx2, float by2) {
    float ix1 = fmaxf(ax1, bx1), iy1 = fmaxf(ay1, by1);
    float ix2 = fminf(ax2, bx2), iy2 = fminf(ay2, by2);
    float inter  = fmaxf(ix2 - ix1, 0.f) * fmaxf(iy2 - iy1, 0.f);
    float area_a = fmaxf(ax2 - ax1, 0.f) * fmaxf(ay2 - ay1, 0.f);
    float area_b = fmaxf(bx2 - bx1, 0.f) * fmaxf(by2 - by1, 0.f);
    float uni = area_a + area_b - inter + 1e-6f;
    float iou = inter / uni;
    float ex1 = fminf(ax1, bx1), ey1 = fminf(ay1, by1);
    float ex2 = fmaxf(ax2, bx2), ey2 = fmaxf(ay2, by2);
    float enc = fmaxf(fmaxf(ex2 - ex1, 0.f) * fmaxf(ey2 - ey1, 0.f), 1e-6f);
    return iou - (enc - uni) / enc;
}

// matching cost (identical floats to R13..R16 — passed)
__device__ __forceinline__ float costf(float4 p, float base2, float ap,
                                       float4 g, float gae) {
    float dx = fminf(p.z, g.z) - fmaxf(p.x, g.x);
    float dy = fminf(p.w, g.w) - fmaxf(p.y, g.y);
    float inter = fmaxf(dx, 0.f) * fmaxf(dy, 0.f);
    float uni = (ap + gae) - inter;
    float ex = fmaxf(p.z, g.z) - fminf(p.x, g.x);
    float ey = fmaxf(p.w, g.w) - fminf(p.y, g.y);
    float enc = fmaxf(fmaxf(ex, 0.f) * fmaxf(ey, 0.f), 1e-6f);
    float ratio = __fdividef(fmaf(uni, uni, inter * enc), uni * enc);
    float l1c = fabsf(p.x - g.x) + fabsf(p.y - g.y) +
                fabsf(p.z - g.z) + fabsf(p.w - g.w);
    return fmaf(-2.f, ratio, fmaf(5.f, l1c, base2));
}

// ===========================================================================
// p1_kernel: compute+store cost rows AND row minima. grid (8, B), 256 thr.
// ===========================================================================
__global__ void __launch_bounds__(HT, 1) p1_kernel(
        const float* __restrict__ pb, const float* __restrict__ pl,
        const float* __restrict__ gb) {
    const int b = blockIdx.y;
    const int tid = threadIdx.x;
    const int lane = tid & 31, wid = tid >> 5;
    const float FINF = FLT_MAX;

    __shared__ float4 pbox4[Q];
    __shared__ float2 baux[Q];

    for (int j = tid; j < Q; j += HT) {
        float4 p = *reinterpret_cast<const float4*>(pb + ((size_t)b * Q + j) * 4);
        pbox4[j] = p;
        float l0 = pl[((size_t)b * Q + j) * 2 + 0];
        float l1 = pl[((size_t)b * Q + j) * 2 + 1];
        float base = -1.0f / (1.0f + __expf(l1 - l0));
        float ap = fmaxf(p.z - p.x, 0.f) * fmaxf(p.w - p.y, 0.f);
        baux[j] = make_float2(base + 2.0f, ap);
    }
    __syncthreads();

    const int r = blockIdx.x * NW + wid;
    float4 g = *reinterpret_cast<const float4*>(gb + ((size_t)b * G + r) * 4);
    float gae = fmaxf(g.z - g.x, 0.f) * fmaxf(g.w - g.y, 0.f) + 1e-6f;
    float* crow = &g_cost[b][r][0];

    float best = FINF; int bj = Q;
#pragma unroll 4
    for (int j = lane; j < Q; j += 32) {
        float2 ba = baux[j];
        float c = costf(pbox4[j], ba.x, ba.y, g, gae);
        crow[j] = c;
        if (c < best) { best = c; bj = j; }
    }
    unsigned ev = fenc(best);
    unsigned vm = __reduce_min_sync(FULLM, ev);
    unsigned jl = (ev == vm) ? (unsigned)bj : 0x7fffffffu;
    unsigned jm = __reduce_min_sync(FULLM, jl);
    if (lane == 0) { g_umin[b][r] = fdec(vm); g_uarg[b][r] = (int)jm; }
}

// ===========================================================================
// match_kernel: P2 + P3 + P4 (scans read stored cost) + losses
// ===========================================================================
__global__ void __launch_bounds__(HT, 1) match_kernel(
        const float* __restrict__ pb, const float* __restrict__ pl,
        const float* __restrict__ gb, float* __restrict__ out) {
    const int b = blockIdx.x;
    const int tid = threadIdx.x;
    const int lane = tid & 31, wid = tid >> 5;
    const float FINF = FLT_MAX;

    __shared__ float  u_sh[G];
    __shared__ short  path[Q];
    __shared__ short  row4col[Q];
    __shared__ short  col4row[G];
    __shared__ int    uarg[G];
    __shared__ short  freerows[FR_CAP];
    __shared__ unsigned long long sl1[2][NW], sl2[2][NW];
    __shared__ double wsum[NW][3];
    __shared__ int    nfree_sh;

    for (int j = tid; j < Q; j += HT) row4col[j] = -1;
    if (tid < G) { u_sh[tid] = g_umin[b][tid]; uarg[tid] = g_uarg[b][tid]; }
    __syncthreads();

    // owner-private per-column state (j = tid + 256k)
    const int nk = (tid < Q - 3 * HT) ? 4 : 3;
    float v_reg[4], spc_reg[4];
    int usedmask = 0;
#pragma unroll
    for (int k = 0; k < 4; k++) { v_reg[k] = 0.f; spc_reg[k] = FINF; }

    // ---- P2: greedy tight-edge assignment ----
    if (tid == 0) {
        int nf = 0;
        for (int r = 0; r < G; r++) {
            int j = uarg[r];
            if (row4col[j] < 0) { row4col[j] = (short)r; col4row[r] = (short)j; }
            else { col4row[r] = -1; freerows[nf++] = (short)r; }
        }
        nfree_sh = nf;
    }
    __syncthreads();

    // ---- P3: augmenting row reduction (LDG cost; REDUX exclude-trick) ----
    {
        int idx = 0, cnt = nfree_sh, iters = 0, par = 0;
        while (idx < cnt && iters < P3_CAP) {
            iters++;
            int i = freerows[idx]; idx++;
            const float* crow = &g_cost[b][i][0];
            unsigned long long k1 = KMAX, k2 = KMAX;
#pragma unroll
            for (int k = 0; k < 4; k++) {
                if (k < nk) {
                    int j = tid + HT * k;
                    float red = __ldg(&crow[j]) - v_reg[k];
                    unsigned long long kk = fkey(red, j);
                    if (kk < k1) { k2 = k1; k1 = kk; }
                    else if (kk < k2) { k2 = kk; }
                }
            }
            // warp top-2 via exclude-trick (keys unique -> exact)
            unsigned long long K1w = warp_kmin(k1);
            unsigned long long cand = (k1 == K1w) ? k2 : k1;
            unsigned long long K2w = warp_kmin(cand);
            if (lane == 0) { sl1[par][wid] = K1w; sl2[par][wid] = K2w; }
            __syncthreads();
            unsigned long long K1 = sl1[par][0], K2 = sl2[par][0];
#pragma unroll
            for (int k = 1; k < NW; k++) {
                unsigned long long o1 = sl1[par][k], o2 = sl2[par][k];
                unsigned long long mx = umax64(K1, o1);
                K1 = umin64(K1, o1);
                K2 = umin64(mx, umin64(K2, o2));
            }
            float m1 = kval(K1), m2 = kval(K2);
            int j1 = kidx(K1), j2 = kidx(K2);
            bool strict = (m1 < m2);
            int jt = j1;
            int i0 = row4col[jt];
            if (!strict && i0 >= 0 && j2 < Q) { jt = j2; i0 = row4col[jt]; }
            __syncthreads();   // order decision-reads before tid0's writes
            if (i0 >= 0) {
                if (strict) idx--;
                else if (cnt < FR_CAP) cnt++;
            }
            if (strict && ((jt & (HT - 1)) == tid)) v_reg[jt >> 8] -= (m2 - m1);
            if (tid == 0) {
                u_sh[i] = m2;
                row4col[jt] = (short)i; col4row[i] = (short)jt;
                if (i0 >= 0) {
                    col4row[i0] = -1;
                    if (strict) freerows[idx] = (short)i0;
                    else if (cnt - 1 < FR_CAP) freerows[cnt - 1] = (short)i0;
                }
            }
            par ^= 1;
            __syncthreads();
        }
    }

    // ---- P4: SAP (LDG cost; reg spc/used/v; REDUX reduce) ----
    for (int cur = 0; cur < G; cur++) {
        if (col4row[cur] >= 0) continue;

        int i = cur, par = 0, sink = -1;
        float minVal = 0.f;

        while (true) {
            float muv = minVal - u_sh[i];
            const float* crow = &g_cost[b][i][0];
            float best = FINF; int bestj = 0x7FFFFFFF;
#pragma unroll
            for (int k = 0; k < 4; k++) {
                if (k < nk && !((usedmask >> k) & 1)) {
                    int j = tid + HT * k;
                    float r = muv + __ldg(&crow[j]) - v_reg[k];
                    float s = spc_reg[k];
                    if (r < s) { s = r; spc_reg[k] = r; path[j] = (short)i; }
                    if (s < best) { best = s; bestj = j; }
                }
            }
            unsigned ev = fenc(best);
            unsigned vm = __reduce_min_sync(FULLM, ev);
            unsigned jl = (ev == vm) ? (unsigned)bestj : 0x7fffffffu;
            unsigned jm = __reduce_min_sync(FULLM, jl);
            if (lane == 0) sl1[par][wid] = ((unsigned long long)vm << 32) | jm;
            __syncthreads();
            unsigned long long K = sl1[par][0];
#pragma unroll
            for (int k = 1; k < NW; k++) K = umin64(K, sl1[par][k]);
            minVal = kval(K);
            int j1 = kidx(K);
            if ((j1 & (HT - 1)) == tid) usedmask |= 1 << (j1 >> 8);
            par ^= 1;
            int nr = row4col[j1];
            if (nr < 0) { sink = j1; break; }
            i = nr;
        }
        __syncthreads();

        // dual updates + owner-private reset
#pragma unroll
        for (int k = 0; k < 4; k++) {
            if (k < nk && ((usedmask >> k) & 1)) {
                int j = tid + HT * k;
                float d = minVal - spc_reg[k];
                int r = row4col[j];
                if (r >= 0) u_sh[r] += d;
                v_reg[k] -= d;
            }
            spc_reg[k] = FINF;
        }
        usedmask = 0;
        __syncthreads();
        if (tid == 0) {
            u_sh[cur] += minVal;
            int j = sink;
            while (true) {
                int i2 = path[j];
                row4col[j] = (short)i2;
                int tcol = col4row[i2];
                col4row[i2] = (short)j;
                j = tcol;
                if (i2 == cur) break;
            }
        }
        __syncthreads();
    }

    // ---- fused per-batch losses (fp64; direct global reads) ----
    double cls = 0.0, bbox = 0.0, gio = 0.0;
    for (int q = tid; q < Q; q += HT) {
        float l0 = pl[((size_t)b * Q + q) * 2 + 0];
        float l1 = pl[((size_t)b * Q + q) * 2 + 1];
        float mx = fmaxf(l0, l1);
        float lse = mx + logf(expf(l0 - mx) + expf(l1 - mx));
        cls += 0.1 * (double)(lse - l1);
    }
    if (tid < G) {
        int g = tid;
        int q = col4row[g];
        float4 mg = *reinterpret_cast<const float4*>(gb + ((size_t)b * G + g) * 4);
        float4 mp = *reinterpret_cast<const float4*>(pb + ((size_t)b * Q + q) * 4);
        bbox = (double)(fabsf(mp.x - mg.x) + fabsf(mp.y - mg.y) +
                        fabsf(mp.z - mg.z) + fabsf(mp.w - mg.w));
        gio = 1.0 - (double)giou_ok(mp.x, mp.y, mp.z, mp.w, mg.x, mg.y, mg.z, mg.w);
        float l0 = pl[((size_t)b * Q + q) * 2 + 0];
        float l1 = pl[((size_t)b * Q + q) * 2 + 1];
        float mx = fmaxf(l0, l1);
        float lse = mx + logf(expf(l0 - mx) + expf(l1 - mx));
        cls += (double)(lse - l0) - 0.1 * (double)(lse - l1);
    }
#pragma unroll
    for (int off = 16; off > 0; off >>= 1) {
        cls  += __shfl_down_sync(FULLM, cls, off);
        bbox += __shfl_down_sync(FULLM, bbox, off);
        gio  += __shfl_down_sync(FULLM, gio, off);
    }
    if (lane == 0) { wsum[wid][0] = cls; wsum[wid][1] = bbox; wsum[wid][2] = gio; }
    __syncthreads();

    if (tid == 0) {
        double cls_t = 0.0, bbox_t = 0.0, gio_t = 0.0;
        for (int w = 0; w < NW; w++) {
            cls_t += wsum[w][0]; bbox_t += wsum[w][1]; gio_t += wsum[w][2];
        }
        g_part[b * 3 + 0] = cls_t;
        g_part[b * 3 + 1] = bbox_t;
        g_part[b * 3 + 2] = gio_t;
        __threadfence();
        int prev = atomicAdd(&g_done, 1);
        if (prev == B - 1) {
            g_done = 0;
            __threadfence();
            double csum = 0.0, bsum = 0.0, gsum = 0.0;
            for (int k = 0; k < B; k++) {
                csum += g_part[k * 3 + 0];
                bsum += g_part[k * 3 + 1];
                gsum += g_part[k * 3 + 2];
            }
            const double wt_sum = 64.0 + (double)(Q - G) * 0.1;  // 157.6
            double lc = (csum / wt_sum) / (double)B;
            double nb = (double)(B * G);
            double lb = bsum / nb;
            double lg = gsum / nb;
            out[0] = (float)(1.0 * lc + 5.0 * lb + 2.0 * lg);
            out[1] = (float)lc;
            out[2] = (float)lb;
            out[3] = (float)lg;
        }
    }
}

// ---------------------------------------------------------------------------
extern "C" void kernel_launch(void* const* d_in, const int* in_sizes, int n_in,
                              void* d_out, int out_size) {
    const float* pred_boxes  = (const float*)d_in[0];  // [32,1000,4]
    const float* pred_logits = (const float*)d_in[1];  // [32,1000,2]
    const float* gt_boxes    = (const float*)d_in[2];  // [32,64,4]
    float* out = (float*)d_out;

    dim3 pgrid(G / NW, B);   // (8, 32) = 256 blocks
    p1_kernel<<<pgrid, HT>>>(pred_boxes, pred_logits, gt_boxes);
    match_kernel<<<B, HT>>>(pred_boxes, pred_logits, gt_boxes, out);
}